// round 2
// baseline (speedup 1.0000x reference)
#include <cuda_runtime.h>
#include <math.h>

// ---------------- Problem constants ----------------
#define BATCH 32
#define CIN   64
#define HIN   64
#define WIN   64
#define KOUT  128
#define OHH   62
#define OWW   62
#define LOC   3844            // OHH*OWW
#define BL    123008          // BATCH*LOC
#define RDIM  576             // CIN*3*3
#define HW    4096            // HIN*WIN
#define Y_ELEMS 15745024      // BATCH*KOUT*LOC

// ---------------- Scratch (no allocations allowed) ----------------
__device__ float g_wT[RDIM * KOUT];   // normalized weight, layout [r][k]
__device__ int   g_winner[BL];
__device__ int   g_counts[KOUT];
__device__ int   g_offsets[KOUT + 1];
__device__ int   g_cursor[KOUT];
__device__ int   g_list[BL];

// ---------------- 1) weight normalize + transpose, zero wu/counters ----------------
__global__ void prep_kernel(const float* __restrict__ w, float* __restrict__ wu) {
    int k = blockIdx.x;
    int tid = threadIdx.x;
    __shared__ float red[256];
    float s = 0.f;
    for (int t = tid; t < RDIM; t += 256) { float v = w[k * RDIM + t]; s += v * v; }
    red[tid] = s;
    __syncthreads();
    for (int off = 128; off > 0; off >>= 1) {
        if (tid < off) red[tid] += red[tid + off];
        __syncthreads();
    }
    __shared__ float s_inv;
    if (tid == 0) {
        float n = sqrtf(red[0]);
        s_inv = (n == 0.f) ? 1.f : (1.f / n);
    }
    __syncthreads();
    float iv = s_inv;
    for (int t = tid; t < RDIM; t += 256) {
        g_wT[t * KOUT + k] = w[k * RDIM + t] * iv;  // [r][k] for conv smem staging
        wu[k * RDIM + t] = 0.f;                     // d_out is poisoned; zero wu region
    }
    if (blockIdx.x == 0 && tid < KOUT) g_counts[tid] = 0;
}

// ---------------- 2) conv: y = x * wn + bias ----------------
// CTA: all 128 k  x  (4 rows x 32 cols) output locations. Thread: 8 k x 8 cols.
#define TOH 4
#define TOW 32
#define SWPAD 132                     // 128 + 4 pad: rotates banks for stride-8 k-groups

__global__ __launch_bounds__(256, 2)
void conv_kernel(const float* __restrict__ x, const float* __restrict__ bias,
                 float* __restrict__ y) {
    __shared__ float sX[8][6][36];    // 8 ch x 6 rows x (34 used, pad->36)
    __shared__ float sW[72][SWPAD];   // (8 ch * 9 taps) x 128 k (+4 pad)

    int tid = threadIdx.x;
    int tx = tid & 15;               // k-group
    int ty = tid >> 4;               // loc-group
    int b   = blockIdx.z;
    int oh0 = blockIdx.y * TOH;
    int ow0 = blockIdx.x * TOW;
    int k0   = tx * 8;
    int lrow = ty >> 2;              // 0..3
    int c0   = (ty & 3) * 8;         // 0,8,16,24

    float acc[8][8];
#pragma unroll
    for (int kk = 0; kk < 8; kk++) {
        float bv = bias[k0 + kk];
#pragma unroll
        for (int u = 0; u < 8; u++) acc[kk][u] = bv;
    }

    const float* xb = x + (size_t)b * (CIN * HW);

    for (int cb = 0; cb < 8; cb++) {          // channel chunks of 8
        __syncthreads();
        // stage x tile: 8ch x 6rows x 34cols (zero-fill out of image).
        // 48 rows of 34 floats; 256 threads -> rows 0..47 handled by tid/... pattern:
        // use 48 row-teams of 5 threads? Simpler: float4 fast path per (row, quad).
        {
            // 8*6 = 48 rows; each row: 8 float4 groups + 2 scalars = 10 slots -> 480 slots
            for (int slot = tid; slot < 480; slot += 256) {
                int row = slot / 10, sub = slot % 10;
                int c = row / 6, rr = row % 6;
                int h = oh0 + rr;
                if (sub < 8) {
                    int col = sub * 4;
                    int wcol = ow0 + col;
                    float4 v = make_float4(0.f, 0.f, 0.f, 0.f);
                    if (h < HIN) {
                        // wcol..wcol+3 all < WIN whenever wcol+3 <= 63; ow0<=32,col<=28 -> wcol<=60 ok
                        v = *(const float4*)(xb + (cb * 8 + c) * HW + h * WIN + wcol);
                    }
                    sX[c][rr][col + 0] = v.x;
                    sX[c][rr][col + 1] = v.y;
                    sX[c][rr][col + 2] = v.z;
                    sX[c][rr][col + 3] = v.w;
                } else {
                    int col = 32 + (sub - 8);
                    int wcol = ow0 + col;
                    float v = 0.f;
                    if (h < HIN && wcol < WIN) v = xb[(cb * 8 + c) * HW + h * WIN + wcol];
                    sX[c][rr][col] = v;
                }
            }
        }
        // stage weights: contiguous 72x128 slab of g_wT into padded rows
        {
            const float4* src = (const float4*)(g_wT + cb * 72 * KOUT);
            for (int idx = tid; idx < 72 * (KOUT / 4); idx += 256) {
                int row = idx >> 5, q = idx & 31;           // 32 float4 per row
                *(float4*)(&sW[row][q * 4]) = src[idx];
            }
        }
        __syncthreads();

        for (int cc = 0; cc < 8; cc++) {      // rolled: keeps body inside L0 I$
#pragma unroll
            for (int i = 0; i < 3; i++) {
                float xw[10];
#pragma unroll
                for (int m = 0; m < 10; m++) xw[m] = sX[cc][lrow + i][c0 + m];
#pragma unroll
                for (int j = 0; j < 3; j++) {
                    float wv[8];
#pragma unroll
                    for (int kk = 0; kk < 8; kk++) wv[kk] = sW[cc * 9 + i * 3 + j][k0 + kk];
#pragma unroll
                    for (int kk = 0; kk < 8; kk++)
#pragma unroll
                        for (int u = 0; u < 8; u++)
                            acc[kk][u] += wv[kk] * xw[j + u];
                }
            }
        }
    }

    int oh = oh0 + lrow;
    if (oh < OHH) {
#pragma unroll
        for (int kk = 0; kk < 8; kk++) {
            float* yp = y + ((size_t)(b * KOUT + k0 + kk)) * LOC + oh * OWW + ow0 + c0;
#pragma unroll
            for (int u = 0; u < 8; u++)
                if (ow0 + c0 + u < OWW) yp[u] = acc[kk][u];
        }
    }
}

// ---------------- 3) argmax over k per location + per-k counts ----------------
__global__ void argmax_kernel(const float* __restrict__ y) {
    int gloc = blockIdx.x * 128 + threadIdx.x;     // 961*128 == BL exactly
    int b = gloc / LOC;
    int il = gloc - b * LOC;
    const float* yb = y + (size_t)b * KOUT * LOC + il;
    float best = yb[0];
    int bk = 0;
#pragma unroll 4
    for (int k = 1; k < KOUT; k++) {
        float v = yb[(size_t)k * LOC];
        if (v > best) { best = v; bk = k; }        // strict '>' => first max (jnp semantics)
    }
    g_winner[gloc] = bk;
    __shared__ int sc[KOUT];
    sc[threadIdx.x] = 0;
    __syncthreads();
    atomicAdd(&sc[bk], 1);
    __syncthreads();
    if (sc[threadIdx.x] > 0) atomicAdd(&g_counts[threadIdx.x], sc[threadIdx.x]);
}

// ---------------- 4) exclusive scan of counts (tiny) ----------------
__global__ void scan_kernel() {
    if (threadIdx.x == 0) {
        int s = 0;
        for (int k = 0; k < KOUT; k++) {
            g_offsets[k] = s;
            g_cursor[k] = s;
            s += g_counts[k];
        }
        g_offsets[KOUT] = s;
    }
}

// ---------------- 5) scatter locations into per-k lists (warp-aggregated) ----------------
__global__ void scatter_kernel() {
    int gloc = blockIdx.x * 128 + threadIdx.x;
    int k = g_winner[gloc];
    unsigned m = __match_any_sync(0xffffffffu, k);
    int lane = threadIdx.x & 31;
    int leader = __ffs(m) - 1;
    int prefix = __popc(m & ((1u << lane) - 1u));
    int base = 0;
    if (lane == leader) base = atomicAdd(&g_cursor[k], __popc(m));
    base = __shfl_sync(0xffffffffu, base, leader);
    g_list[base + prefix] = gloc;
}

// ---------------- 6) Hebbian gather: wu[k,r] = scale * sum_{loc in list_k} patch[r] ----------------
#define NSPLIT 8
__global__ __launch_bounds__(192)
void hebb_kernel(const float* __restrict__ x, float* __restrict__ wu) {
    int k = blockIdx.y;
    int start = g_offsets[k], end = g_offsets[k + 1];
    int len = end - start;
    int s0 = start + (int)((long long)len * blockIdx.x / NSPLIT);
    int s1 = start + (int)((long long)len * (blockIdx.x + 1) / NSPLIT);
    int t = threadIdx.x;

    int off[3];
    float a[3] = {0.f, 0.f, 0.f};
#pragma unroll
    for (int q = 0; q < 3; q++) {
        int r = t + q * 192;
        int c = r / 9, rem = r % 9;
        off[q] = c * HW + (rem / 3) * WIN + (rem % 3);
    }

    if (s0 < s1) {
        int nextg = g_list[s0];                     // prefetch list head
        for (int p = s0; p < s1; p++) {
            int gloc = nextg;
            if (p + 1 < s1) nextg = g_list[p + 1];  // hide broadcast LDG behind body
            int b = gloc / LOC;
            int il = gloc - b * LOC;
            int oh = il / OWW;
            int ow = il - oh * OWW;
            const float* px = x + (size_t)b * (CIN * HW) + oh * WIN + ow;
            a[0] += px[off[0]];
            a[1] += px[off[1]];
            a[2] += px[off[2]];
        }
    }

    const float scale = 1.0f / 123008.0f;      // 1/(B*L + 1e-8) == 1/123008 in fp32
#pragma unroll
    for (int q = 0; q < 3; q++)
        atomicAdd(&wu[k * RDIM + t + q * 192], a[q] * scale);
}

// ---------------- launch ----------------
extern "C" void kernel_launch(void* const* d_in, const int* in_sizes, int n_in,
                              void* d_out, int out_size) {
    const float* x    = (const float*)d_in[0];   // [32,64,64,64]
    const float* w    = (const float*)d_in[1];   // [128,64,3,3]
    const float* bias = (const float*)d_in[2];   // [128]
    float* y  = (float*)d_out;                   // [32,128,62,62]
    float* wu = y + (size_t)Y_ELEMS;             // [128,64,3,3]

    prep_kernel<<<KOUT, 256>>>(w, wu);
    conv_kernel<<<dim3(2, 16, BATCH), 256>>>(x, bias, y);
    argmax_kernel<<<BL / 128, 128>>>(y);
    scan_kernel<<<1, 32>>>();
    scatter_kernel<<<BL / 128, 128>>>();
    hebb_kernel<<<dim3(NSPLIT, KOUT), 192>>>(x, wu);
}

// round 3
// speedup vs baseline: 1.1910x; 1.1910x over previous
#include <cuda_runtime.h>
#include <math.h>

// ---------------- Problem constants ----------------
#define BATCH 32
#define CIN   64
#define HIN   64
#define WIN   64
#define KOUT  128
#define OHH   62
#define OWW   62
#define LOC   3844            // OHH*OWW
#define BL    123008          // BATCH*LOC
#define RDIM  576             // CIN*3*3
#define HW    4096            // HIN*WIN
#define Y_ELEMS 15745024      // BATCH*KOUT*LOC

typedef unsigned long long u64;

// ---------------- Scratch (no allocations allowed) ----------------
__device__ float g_wT[RDIM * KOUT];   // normalized weight, layout [r][k]
__device__ int   g_winner[BL];
__device__ int   g_counts[KOUT];
__device__ int   g_offsets[KOUT + 1];
__device__ int   g_cursor[KOUT];
__device__ int   g_list[BL];

// f32x2 helpers (sm_100a packed fp32)
__device__ __forceinline__ u64 pack_dup(float x) {
    u64 r;
    asm("mov.b64 %0, {%1, %2};" : "=l"(r) : "f"(x), "f"(x));
    return r;
}
__device__ __forceinline__ void fma2(u64& d, u64 a, u64 b) {
    asm("fma.rn.f32x2 %0, %1, %2, %0;" : "+l"(d) : "l"(a), "l"(b));
}
__device__ __forceinline__ float2 unpack2(u64 v) {
    float2 r;
    asm("mov.b64 {%0, %1}, %2;" : "=f"(r.x), "=f"(r.y) : "l"(v));
    return r;
}

// ---------------- 1) weight normalize + transpose, zero wu/counters ----------------
__global__ void prep_kernel(const float* __restrict__ w, float* __restrict__ wu) {
    int k = blockIdx.x;
    int tid = threadIdx.x;
    __shared__ float red[256];
    float s = 0.f;
    for (int t = tid; t < RDIM; t += 256) { float v = w[k * RDIM + t]; s += v * v; }
    red[tid] = s;
    __syncthreads();
    for (int off = 128; off > 0; off >>= 1) {
        if (tid < off) red[tid] += red[tid + off];
        __syncthreads();
    }
    __shared__ float s_inv;
    if (tid == 0) {
        float n = sqrtf(red[0]);
        s_inv = (n == 0.f) ? 1.f : (1.f / n);
    }
    __syncthreads();
    float iv = s_inv;
    for (int t = tid; t < RDIM; t += 256) {
        g_wT[t * KOUT + k] = w[k * RDIM + t] * iv;  // [r][k] for conv smem staging
        wu[k * RDIM + t] = 0.f;                     // d_out is poisoned; zero wu region
    }
    if (blockIdx.x == 0 && tid < KOUT) g_counts[tid] = 0;
}

// ---------------- 2) conv: y = x * wn + bias (f32x2 packed) ----------------
// CTA: all 128 k x (4 rows x 32 cols). Thread: k = 2*tx + 32*q + r (q=0..3, r=0..1), 8 cols.
#define TOH 4
#define TOW 32

__global__ __launch_bounds__(256, 2)
void conv_kernel(const float* __restrict__ x, const float* __restrict__ bias,
                 float* __restrict__ y) {
    __shared__ float sX[8][6][36];    // 8 ch x 6 rows x (34 used, pad->36)
    __shared__ float sW[72][KOUT];    // (8 ch * 9 taps) x 128 k

    int tid = threadIdx.x;
    int tx = tid & 15;               // k-lane
    int ty = tid >> 4;               // loc-group
    int b   = blockIdx.z;
    int oh0 = blockIdx.y * TOH;
    int ow0 = blockIdx.x * TOW;
    int kb   = tx * 2;               // pair base; groups at kb + 32*q
    int lrow = ty >> 2;              // 0..3
    int c0   = (ty & 3) * 8;         // 0,8,16,24

    u64 acc[4][8];                   // [q][u] = (k=kb+32q, k=kb+32q+1)
#pragma unroll
    for (int q = 0; q < 4; q++) {
        u64 bv = *(const u64*)(bias + kb + 32 * q);   // 8B-aligned (kb even)
#pragma unroll
        for (int u = 0; u < 8; u++) acc[q][u] = bv;
    }

    const float* xb = x + (size_t)b * (CIN * HW);

    for (int cb = 0; cb < 8; cb++) {          // channel chunks of 8
        __syncthreads();
        // stage x tile: 8ch x 6rows x 34cols (float4 fast path + 2 scalars per row)
        for (int slot = tid; slot < 480; slot += 256) {
            int row = slot / 10, sub = slot % 10;
            int c = row / 6, rr = row % 6;
            int h = oh0 + rr;
            if (sub < 8) {
                int col = sub * 4;
                float4 v = make_float4(0.f, 0.f, 0.f, 0.f);
                if (h < HIN) v = *(const float4*)(xb + (cb * 8 + c) * HW + h * WIN + ow0 + col);
                sX[c][rr][col + 0] = v.x;
                sX[c][rr][col + 1] = v.y;
                sX[c][rr][col + 2] = v.z;
                sX[c][rr][col + 3] = v.w;
            } else {
                int col = 32 + (sub - 8);
                int wcol = ow0 + col;
                float v = 0.f;
                if (h < HIN && wcol < WIN) v = xb[(cb * 8 + c) * HW + h * WIN + wcol];
                sX[c][rr][col] = v;
            }
        }
        // stage weights: contiguous 72x128 slab of g_wT
        {
            const float4* src = (const float4*)(g_wT + cb * 72 * KOUT);
            float4* dst = (float4*)(&sW[0][0]);
            for (int idx = tid; idx < 72 * (KOUT / 4); idx += 256) dst[idx] = src[idx];
        }
        __syncthreads();

        for (int cc = 0; cc < 8; cc++) {      // rolled: keeps body inside L0 I$
#pragma unroll
            for (int i = 0; i < 3; i++) {
                u64 xd[10];
#pragma unroll
                for (int m = 0; m < 10; m++) xd[m] = pack_dup(sX[cc][lrow + i][c0 + m]);
#pragma unroll
                for (int j = 0; j < 3; j++) {
                    const float* wrow = &sW[cc * 9 + i * 3 + j][0];
                    u64 w2[4];
#pragma unroll
                    for (int q = 0; q < 4; q++)
                        w2[q] = *(const u64*)(wrow + kb + 32 * q);  // contiguous 128B across lanes
#pragma unroll
                    for (int q = 0; q < 4; q++)
#pragma unroll
                        for (int u = 0; u < 8; u++)
                            fma2(acc[q][u], w2[q], xd[j + u]);
                }
            }
        }
    }

    int oh = oh0 + lrow;
    if (oh < OHH) {
#pragma unroll
        for (int q = 0; q < 4; q++) {
            int k = kb + 32 * q;
            float* yp0 = y + ((size_t)(b * KOUT + k)) * LOC + oh * OWW + ow0 + c0;
            float* yp1 = yp0 + LOC;
#pragma unroll
            for (int u = 0; u < 8; u++) {
                if (ow0 + c0 + u < OWW) {
                    float2 v = unpack2(acc[q][u]);
                    yp0[u] = v.x;
                    yp1[u] = v.y;
                }
            }
        }
    }
}

// ---------------- 3) argmax over k per location + per-k counts ----------------
__global__ void argmax_kernel(const float* __restrict__ y) {
    int gloc = blockIdx.x * 128 + threadIdx.x;     // 961*128 == BL exactly
    int b = gloc / LOC;
    int il = gloc - b * LOC;
    const float* yb = y + (size_t)b * KOUT * LOC + il;
    float best = yb[0];
    int bk = 0;
#pragma unroll 4
    for (int k = 1; k < KOUT; k++) {
        float v = yb[(size_t)k * LOC];
        if (v > best) { best = v; bk = k; }        // strict '>' => first max (jnp semantics)
    }
    g_winner[gloc] = bk;
    __shared__ int sc[KOUT];
    sc[threadIdx.x] = 0;
    __syncthreads();
    atomicAdd(&sc[bk], 1);
    __syncthreads();
    if (sc[threadIdx.x] > 0) atomicAdd(&g_counts[threadIdx.x], sc[threadIdx.x]);
}

// ---------------- 4) exclusive scan of counts (parallel, 128 threads) ----------------
__global__ void scan_kernel() {
    int t = threadIdx.x;               // 128
    int lane = t & 31, w = t >> 5;
    int v = g_counts[t];
    int inc = v;
#pragma unroll
    for (int o = 1; o < 32; o <<= 1) {
        int n = __shfl_up_sync(0xffffffffu, inc, o);
        if (lane >= o) inc += n;
    }
    __shared__ int wsum[4];
    if (lane == 31) wsum[w] = inc;
    __syncthreads();
    int add = 0;
#pragma unroll
    for (int i = 0; i < 4; i++) if (i < w) add += wsum[i];
    int excl = inc - v + add;
    g_offsets[t] = excl;
    g_cursor[t] = excl;
    if (t == 127) g_offsets[KOUT] = excl + v;
}

// ---------------- 5) scatter locations into per-k lists (warp-aggregated) ----------------
__global__ void scatter_kernel() {
    int gloc = blockIdx.x * 128 + threadIdx.x;
    int k = g_winner[gloc];
    unsigned m = __match_any_sync(0xffffffffu, k);
    int lane = threadIdx.x & 31;
    int leader = __ffs(m) - 1;
    int prefix = __popc(m & ((1u << lane) - 1u));
    int base = 0;
    if (lane == leader) base = atomicAdd(&g_cursor[k], __popc(m));
    base = __shfl_sync(0xffffffffu, base, leader);
    g_list[base + prefix] = gloc;
}

// ---------------- 6) Hebbian gather: wu[k,r] = scale * sum_{loc in list_k} patch[r] ----------------
#define NSPLIT 8
__global__ __launch_bounds__(192)
void hebb_kernel(const float* __restrict__ x, float* __restrict__ wu) {
    int k = blockIdx.y;
    int start = g_offsets[k], end = g_offsets[k + 1];
    int len = end - start;
    int s0 = start + (int)((long long)len * blockIdx.x / NSPLIT);
    int s1 = start + (int)((long long)len * (blockIdx.x + 1) / NSPLIT);
    int t = threadIdx.x;

    int off[3];
    float a[3] = {0.f, 0.f, 0.f};
#pragma unroll
    for (int q = 0; q < 3; q++) {
        int r = t + q * 192;
        int c = r / 9, rem = r % 9;
        off[q] = c * HW + (rem / 3) * WIN + (rem % 3);
    }

    if (s0 < s1) {
        int nextg = g_list[s0];                     // prefetch list head
        for (int p = s0; p < s1; p++) {
            int gloc = nextg;
            if (p + 1 < s1) nextg = g_list[p + 1];  // hide broadcast LDG behind body
            int b = gloc / LOC;
            int il = gloc - b * LOC;
            int oh = il / OWW;
            int ow = il - oh * OWW;
            const float* px = x + (size_t)b * (CIN * HW) + oh * WIN + ow;
            a[0] += px[off[0]];
            a[1] += px[off[1]];
            a[2] += px[off[2]];
        }
    }

    const float scale = 1.0f / 123008.0f;      // 1/(B*L + 1e-8) == 1/123008 in fp32
#pragma unroll
    for (int q = 0; q < 3; q++)
        atomicAdd(&wu[k * RDIM + t + q * 192], a[q] * scale);
}

// ---------------- launch ----------------
extern "C" void kernel_launch(void* const* d_in, const int* in_sizes, int n_in,
                              void* d_out, int out_size) {
    const float* x    = (const float*)d_in[0];   // [32,64,64,64]
    const float* w    = (const float*)d_in[1];   // [128,64,3,3]
    const float* bias = (const float*)d_in[2];   // [128]
    float* y  = (float*)d_out;                   // [32,128,62,62]
    float* wu = y + (size_t)Y_ELEMS;             // [128,64,3,3]

    prep_kernel<<<KOUT, 256>>>(w, wu);
    conv_kernel<<<dim3(2, 16, BATCH), 256>>>(x, bias, y);
    argmax_kernel<<<BL / 128, 128>>>(y);
    scan_kernel<<<1, 128>>>();
    scatter_kernel<<<BL / 128, 128>>>();
    hebb_kernel<<<dim3(NSPLIT, KOUT), 192>>>(x, wu);
}

// round 4
// speedup vs baseline: 1.1977x; 1.0057x over previous
#include <cuda_runtime.h>
#include <math.h>

// ---------------- Problem constants ----------------
#define BATCH 32
#define CIN   64
#define HIN   64
#define WIN   64
#define KOUT  128
#define OHH   62
#define OWW   62
#define LOC   3844            // OHH*OWW
#define BL    123008          // BATCH*LOC
#define RDIM  576             // CIN*3*3
#define HW    4096            // HIN*WIN
#define Y_ELEMS 15745024      // BATCH*KOUT*LOC

typedef unsigned long long u64;

// ---------------- Scratch (no allocations allowed) ----------------
__device__ float g_wT[RDIM * KOUT];   // normalized weight, layout [r][k]
__device__ float g_winv[KOUT];
__device__ int   g_winner[BL];
__device__ int   g_counts[KOUT];
__device__ int   g_offsets[KOUT + 1];
__device__ int   g_cursor[KOUT];
__device__ int   g_list[BL];

// f32x2 helpers (sm_100a packed fp32)
__device__ __forceinline__ u64 pack_dup(float x) {
    u64 r;
    asm("mov.b64 %0, {%1, %2};" : "=l"(r) : "f"(x), "f"(x));
    return r;
}
__device__ __forceinline__ void fma2(u64& d, u64 a, u64 b) {
    asm("fma.rn.f32x2 %0, %1, %2, %0;" : "+l"(d) : "l"(a), "l"(b));
}
__device__ __forceinline__ float2 unpack2(u64 v) {
    float2 r;
    asm("mov.b64 {%0, %1}, %2;" : "=f"(r.x), "=f"(r.y) : "l"(v));
    return r;
}

// ---------------- 1a) per-k inverse weight norm ----------------
__global__ void norm_kernel(const float* __restrict__ w) {
    int k = blockIdx.x;
    int tid = threadIdx.x;
    __shared__ float red[256];
    float s = 0.f;
    for (int t = tid; t < RDIM; t += 256) { float v = w[k * RDIM + t]; s += v * v; }
    red[tid] = s;
    __syncthreads();
    for (int off = 128; off > 0; off >>= 1) {
        if (tid < off) red[tid] += red[tid + off];
        __syncthreads();
    }
    if (tid == 0) {
        float n = sqrtf(red[0]);
        g_winv[k] = (n == 0.f) ? 1.f : (1.f / n);
    }
}

// ---------------- 1b) transpose normalized weights, zero wu ----------------
__global__ void wtrans_kernel(const float* __restrict__ w, float* __restrict__ wu) {
    int k = blockIdx.x;
    int tid = threadIdx.x;
    float iv = g_winv[k];
    for (int t = tid; t < RDIM; t += 256) {
        g_wT[t * KOUT + k] = w[k * RDIM + t] * iv;
        wu[k * RDIM + t] = 0.f;
    }
}

// ---------------- 1c) zero winner counters ----------------
__global__ void zcnt_kernel() { g_counts[threadIdx.x] = 0; }

// ---------------- 2) conv + fused argmax/count ----------------
// CTA: all 128 k x (4 rows x 32 cols). Thread: k = 2*tx + 32*q + r, 8 cols.
#define TOH 4
#define TOW 32

__global__ __launch_bounds__(256, 2)
void conv_kernel(const float* __restrict__ x, const float* __restrict__ bias,
                 float* __restrict__ y) {
    __shared__ float sX[8][6][36];    // 8 ch x 6 rows x (34 used, pad->36)
    __shared__ float sW[72][KOUT];    // (8 ch * 9 taps) x 128 k
    __shared__ int scount[KOUT];

    int tid = threadIdx.x;
    int tx = tid & 15;               // k-lane
    int ty = tid >> 4;               // loc-group
    int b   = blockIdx.z;
    int oh0 = blockIdx.y * TOH;
    int ow0 = blockIdx.x * TOW;
    int kb   = tx * 2;               // pair base; groups at kb + 32*q
    int lrow = ty >> 2;              // 0..3
    int c0   = (ty & 3) * 8;         // 0,8,16,24

    if (tid < KOUT) scount[tid] = 0;

    u64 acc[4][8];                   // [q][u] = (k=kb+32q, k=kb+32q+1)
#pragma unroll
    for (int q = 0; q < 4; q++) {
        u64 bv = *(const u64*)(bias + kb + 32 * q);   // 8B-aligned (kb even)
#pragma unroll
        for (int u = 0; u < 8; u++) acc[q][u] = bv;
    }

    const float* xb = x + (size_t)b * (CIN * HW);

    for (int cb = 0; cb < 8; cb++) {          // channel chunks of 8
        __syncthreads();
        // stage x tile: 8ch x 6rows x 34cols (float4 fast path + 2 scalars per row)
        for (int slot = tid; slot < 480; slot += 256) {
            int row = slot / 10, sub = slot % 10;
            int c = row / 6, rr = row % 6;
            int h = oh0 + rr;
            if (sub < 8) {
                int col = sub * 4;
                float4 v = make_float4(0.f, 0.f, 0.f, 0.f);
                if (h < HIN) v = *(const float4*)(xb + (cb * 8 + c) * HW + h * WIN + ow0 + col);
                sX[c][rr][col + 0] = v.x;
                sX[c][rr][col + 1] = v.y;
                sX[c][rr][col + 2] = v.z;
                sX[c][rr][col + 3] = v.w;
            } else {
                int col = 32 + (sub - 8);
                int wcol = ow0 + col;
                float v = 0.f;
                if (h < HIN && wcol < WIN) v = xb[(cb * 8 + c) * HW + h * WIN + wcol];
                sX[c][rr][col] = v;
            }
        }
        // stage weights: contiguous 72x128 slab of g_wT
        {
            const float4* src = (const float4*)(g_wT + cb * 72 * KOUT);
            float4* dst = (float4*)(&sW[0][0]);
            for (int idx = tid; idx < 72 * (KOUT / 4); idx += 256) dst[idx] = src[idx];
        }
        __syncthreads();

        for (int cc = 0; cc < 8; cc++) {      // rolled: keeps body inside L0 I$
#pragma unroll
            for (int i = 0; i < 3; i++) {
                u64 xd[10];
#pragma unroll
                for (int m = 0; m < 10; m++) xd[m] = pack_dup(sX[cc][lrow + i][c0 + m]);
#pragma unroll
                for (int j = 0; j < 3; j++) {
                    const float* wrow = &sW[cc * 9 + i * 3 + j][0];
                    u64 w2[4];
#pragma unroll
                    for (int q = 0; q < 4; q++)
                        w2[q] = *(const u64*)(wrow + kb + 32 * q);  // contiguous 128B across lanes
#pragma unroll
                    for (int q = 0; q < 4; q++)
#pragma unroll
                        for (int u = 0; u < 8; u++)
                            fma2(acc[q][u], w2[q], xd[j + u]);
                }
            }
        }
    }

    int oh = oh0 + lrow;
    bool rowok = (oh < OHH);

    // y store + fused argmax per location
#pragma unroll
    for (int u = 0; u < 8; u++) {
        int ow = ow0 + c0 + u;
        // local first-max over this thread's 8 k values
        float2 v0 = unpack2(acc[0][u]);
        float best = v0.x; int bk = kb;
        if (v0.y > best) { best = v0.y; bk = kb + 1; }
#pragma unroll
        for (int q = 1; q < 4; q++) {
            float2 v = unpack2(acc[q][u]);
            int kq = kb + 32 * q;
            if (v.x > best) { best = v.x; bk = kq; }
            if (v.y > best) { best = v.y; bk = kq + 1; }
        }
        // butterfly over the 16 k-lanes (first-max tie-break: smaller k)
#pragma unroll
        for (int o = 1; o < 16; o <<= 1) {
            float v2 = __shfl_xor_sync(0xffffffffu, best, o);
            int   k2 = __shfl_xor_sync(0xffffffffu, bk,   o);
            if (v2 > best || (v2 == best && k2 < bk)) { best = v2; bk = k2; }
        }
        if (rowok && ow < OWW) {
            if (tx == 0) {
                g_winner[b * LOC + oh * OWW + ow] = bk;
                atomicAdd(&scount[bk], 1);
            }
        }
    }

    // y stores
    if (rowok) {
#pragma unroll
        for (int q = 0; q < 4; q++) {
            int k = kb + 32 * q;
            float* yp0 = y + ((size_t)(b * KOUT + k)) * LOC + oh * OWW + ow0 + c0;
            float* yp1 = yp0 + LOC;
#pragma unroll
            for (int u = 0; u < 8; u++) {
                if (ow0 + c0 + u < OWW) {
                    float2 v = unpack2(acc[q][u]);
                    yp0[u] = v.x;
                    yp1[u] = v.y;
                }
            }
        }
    }

    __syncthreads();
    if (tid < KOUT && scount[tid]) atomicAdd(&g_counts[tid], scount[tid]);
}

// ---------------- 3) exclusive scan of counts (parallel, 128 threads) ----------------
__global__ void scan_kernel() {
    int t = threadIdx.x;               // 128
    int lane = t & 31, w = t >> 5;
    int v = g_counts[t];
    int inc = v;
#pragma unroll
    for (int o = 1; o < 32; o <<= 1) {
        int n = __shfl_up_sync(0xffffffffu, inc, o);
        if (lane >= o) inc += n;
    }
    __shared__ int wsum[4];
    if (lane == 31) wsum[w] = inc;
    __syncthreads();
    int add = 0;
#pragma unroll
    for (int i = 0; i < 4; i++) if (i < w) add += wsum[i];
    int excl = inc - v + add;
    g_offsets[t] = excl;
    g_cursor[t] = excl;
    if (t == 127) g_offsets[KOUT] = excl + v;
}

// ---------------- 4) scatter locations into per-k lists (warp-aggregated) ----------------
__global__ void scatter_kernel() {
    int gloc = blockIdx.x * 128 + threadIdx.x;
    int k = g_winner[gloc];
    unsigned m = __match_any_sync(0xffffffffu, k);
    int lane = threadIdx.x & 31;
    int leader = __ffs(m) - 1;
    int prefix = __popc(m & ((1u << lane) - 1u));
    int base = 0;
    if (lane == leader) base = atomicAdd(&g_cursor[k], __popc(m));
    base = __shfl_sync(0xffffffffu, base, leader);
    g_list[base + prefix] = gloc;
}

// ---------------- 5) Hebbian gather: wu[k,r] = scale * sum_{loc in list_k} patch[r] ----------------
#define NSPLIT 8
__global__ __launch_bounds__(192)
void hebb_kernel(const float* __restrict__ x, float* __restrict__ wu) {
    int k = blockIdx.y;
    int start = g_offsets[k], end = g_offsets[k + 1];
    int len = end - start;
    int s0 = start + (int)((long long)len * blockIdx.x / NSPLIT);
    int s1 = start + (int)((long long)len * (blockIdx.x + 1) / NSPLIT);
    int t = threadIdx.x;

    int off[3];
    float a[3] = {0.f, 0.f, 0.f};
#pragma unroll
    for (int q = 0; q < 3; q++) {
        int r = t + q * 192;
        int c = r / 9, rem = r % 9;
        off[q] = c * HW + (rem / 3) * WIN + (rem % 3);
    }

    if (s0 < s1) {
        int nextg = g_list[s0];                     // prefetch list head
        for (int p = s0; p < s1; p++) {
            int gloc = nextg;
            if (p + 1 < s1) nextg = g_list[p + 1];  // hide broadcast LDG behind body
            int b = gloc / LOC;
            int il = gloc - b * LOC;
            int oh = il / OWW;
            int ow = il - oh * OWW;
            const float* px = x + (size_t)b * (CIN * HW) + oh * WIN + ow;
            a[0] += px[off[0]];
            a[1] += px[off[1]];
            a[2] += px[off[2]];
        }
    }

    const float scale = 1.0f / 123008.0f;      // 1/(B*L + 1e-8) == 1/123008 in fp32
#pragma unroll
    for (int q = 0; q < 3; q++)
        atomicAdd(&wu[k * RDIM + t + q * 192], a[q] * scale);
}

// ---------------- launch ----------------
// Order matters: ncu capture lands on the 4th launch -> conv gets profiled.
extern "C" void kernel_launch(void* const* d_in, const int* in_sizes, int n_in,
                              void* d_out, int out_size) {
    const float* x    = (const float*)d_in[0];   // [32,64,64,64]
    const float* w    = (const float*)d_in[1];   // [128,64,3,3]
    const float* bias = (const float*)d_in[2];   // [128]
    float* y  = (float*)d_out;                   // [32,128,62,62]
    float* wu = y + (size_t)Y_ELEMS;             // [128,64,3,3]

    norm_kernel<<<KOUT, 256>>>(w);               // 1
    wtrans_kernel<<<KOUT, 256>>>(w, wu);         // 2
    zcnt_kernel<<<1, KOUT>>>();                  // 3
    conv_kernel<<<dim3(2, 16, BATCH), 256>>>(x, bias, y);  // 4  <- profiled slot
    scan_kernel<<<1, 128>>>();                   // 5
    scatter_kernel<<<BL / 128, 128>>>();         // 6
    hebb_kernel<<<dim3(NSPLIT, KOUT), 192>>>(x, wu);       // 7
}